// round 15
// baseline (speedup 1.0000x reference)
#include <cuda_runtime.h>
#include <cuda_fp16.h>

#define N_NODES 4096
#define HEADS   8
#define OUTF    256
#define NCHUNK  2
#define JT      128
#define ITILE   64
#define JCHUNK  (N_NODES / NCHUNK)
#define NTILES  (JCHUNK / JT)

// ---------------- device scratch ----------------
__device__ __align__(16) __half   g_h_t[OUTF * N_NODES];       // [h*32+f][n] fp16
__device__ __align__(16) float    Wa_g[256 * 16];
__device__ __align__(16) __half2  PR_g[HEADS * N_NODES];
__device__ __align__(16) __half   qg[HEADS * N_NODES];
__device__ __align__(16) __half   tg[HEADS * N_NODES];
__device__ __align__(16) unsigned adj_bits[N_NODES * (N_NODES / 32)];
__device__ __align__(16) float    num_part[NCHUNK][N_NODES][OUTF];
__device__ __align__(16) float    z_part[NCHUNK][HEADS][N_NODES];

// ---------------- tf32 helpers ----------------
__device__ __forceinline__ unsigned tf32r(float x) {
    unsigned y;
    asm("cvt.rna.tf32.f32 %0, %1;" : "=r"(y) : "f"(x));
    return y;
}

__device__ __forceinline__ void mma_tf32(float* c, unsigned a0, unsigned a1,
                                         unsigned a2, unsigned a3,
                                         unsigned b0, unsigned b1) {
    asm volatile(
        "mma.sync.aligned.m16n8k8.row.col.f32.tf32.tf32.f32 "
        "{%0,%1,%2,%3}, {%4,%5,%6,%7}, {%8,%9}, {%0,%1,%2,%3};"
        : "+f"(c[0]), "+f"(c[1]), "+f"(c[2]), "+f"(c[3])
        : "r"(a0), "r"(a1), "r"(a2), "r"(a3), "r"(b0), "r"(b1));
}

// gemm branch smem: sh_w [256][68] u32 (69632) | sh_h [2][64][36] u32 (18432) = 88064
#define PREP_SMEM 88064

// ================= fused prep kernel =================
// blocks [0,32): compute_wa   | [32,288): gemm 64m x 64n | [288,2336): adj_to_bits
__global__ __launch_bounds__(256, 2) void prep_fused(const float* __restrict__ h,
                                                     const float* __restrict__ W,
                                                     const float* __restrict__ a,
                                                     const int* __restrict__ adj) {
    extern __shared__ unsigned smg[];
    int bx = blockIdx.x;
    int tid = threadIdx.x;
    int warp = tid >> 5, lane = tid & 31;

    if (bx < 32) {
        // ---- compute_wa ----
        int k = bx * 8 + warp;
        float wrow[8];
#pragma unroll
        for (int hd = 0; hd < 8; hd++) wrow[hd] = W[(size_t)k * 256 + hd * 32 + lane];
        float asrc = a[lane], adst = a[32 + lane];
#pragma unroll
        for (int c = 0; c < 16; c++) {
            float v = wrow[c & 7] * ((c < 8) ? asrc : adst);
#pragma unroll
            for (int o = 16; o; o >>= 1) v += __shfl_xor_sync(0xffffffffu, v, o);
            if (lane == 0) Wa_g[k * 16 + c] = v;
        }
        return;
    }

    if (bx >= 288) {
        // ---- adj_to_bits ----
        int ga = bx - 288;
        int gw = ga * 8 + warp;
        int i = gw >> 2, wbase = (gw & 3) * 32;
#pragma unroll 8
        for (int k = 0; k < 32; k++) {
            int v = adj[(size_t)i * N_NODES + (wbase + k) * 32 + lane];
            unsigned b = __ballot_sync(0xffffffffu, v != 0);
            if (lane == 0) adj_bits[i * 128 + wbase + k] = b;
        }
        return;
    }

    // ---- gemm: g = h @ W (64m x 64n, tf32) ----
    int g = bx - 32;
    int n0 = (g & 3) * 64, m0 = (g >> 2) * 64;

    unsigned* sh_w = smg;                    // [k(256)][68]
    unsigned* sh_h = smg + 256 * 68;         // [2][m(64)][36]
    __half* tT = (__half*)smg;               // epilogue alias: [64][136] halves

    int gid = lane >> 2, tig = lane & 3;
    int wm = warp >> 2, wn = warp & 3;       // warp tile: m 32, n 16

    // stage W[:, n0:n0+64] -> tf32 : 4096 float4
#pragma unroll
    for (int i = 0; i < 16; i++) {
        int idx = i * 256 + tid;
        int k = idx >> 4, seg = idx & 15;
        float4 v = *(const float4*)&W[(size_t)k * 256 + n0 + seg * 4];
        uint4 u = make_uint4(tf32r(v.x), tf32r(v.y), tf32r(v.z), tf32r(v.w));
        *(uint4*)&sh_w[k * 68 + seg * 4] = u;
    }

    float4 hreg[2];
    auto ldh = [&](int kc) {
#pragma unroll
        for (int i = 0; i < 2; i++) {
            int idx = i * 256 + tid;
            int m = idx >> 3, seg = idx & 7;
            hreg[i] = *(const float4*)&h[(size_t)(m0 + m) * 256 + kc * 32 + seg * 4];
        }
    };
    auto sth = [&](int b) {
        unsigned* dst = sh_h + b * 64 * 36;
#pragma unroll
        for (int i = 0; i < 2; i++) {
            int idx = i * 256 + tid;
            int m = idx >> 3, seg = idx & 7;
            float4 v = hreg[i];
            uint4 u = make_uint4(tf32r(v.x), tf32r(v.y), tf32r(v.z), tf32r(v.w));
            *(uint4*)&dst[m * 36 + seg * 4] = u;
        }
    };

    float c[2][2][4] = {};

    ldh(0);
    for (int kc = 0; kc < 8; kc++) {
        sth(kc & 1);
        __syncthreads();
        if (kc < 7) ldh(kc + 1);

        const unsigned* A = sh_h + (kc & 1) * 64 * 36;
#pragma unroll
        for (int ks = 0; ks < 4; ks++) {
            unsigned b0[2], b1[2];
            int kb = kc * 32 + ks * 8 + tig;
#pragma unroll
            for (int nt = 0; nt < 2; nt++) {
                int nn = wn * 16 + nt * 8 + gid;
                b0[nt] = sh_w[kb * 68 + nn];
                b1[nt] = sh_w[(kb + 4) * 68 + nn];
            }
#pragma unroll
            for (int mt = 0; mt < 2; mt++) {
                int r0 = (wm * 32 + mt * 16 + gid) * 36 + ks * 8 + tig;
                unsigned a0 = A[r0];
                unsigned a1 = A[r0 + 8 * 36];
                unsigned a2 = A[r0 + 4];
                unsigned a3 = A[r0 + 8 * 36 + 4];
#pragma unroll
                for (int nt = 0; nt < 2; nt++)
                    mma_tf32(c[mt][nt], a0, a1, a2, a3, b0[nt], b1[nt]);
            }
        }
        __syncthreads();
    }

    // epilogue: fragments -> tT[n][m] halves -> coalesced global (transposed)
#pragma unroll
    for (int mt = 0; mt < 2; mt++)
#pragma unroll
        for (int nt = 0; nt < 2; nt++) {
            int nn = wn * 16 + nt * 8 + tig * 2;
            int mm = wm * 32 + mt * 16 + gid;
            tT[nn * 136 + mm]           = __float2half(c[mt][nt][0]);
            tT[(nn + 1) * 136 + mm]     = __float2half(c[mt][nt][1]);
            tT[nn * 136 + mm + 8]       = __float2half(c[mt][nt][2]);
            tT[(nn + 1) * 136 + mm + 8] = __float2half(c[mt][nt][3]);
        }
    __syncthreads();
#pragma unroll
    for (int i = 0; i < 2; i++) {
        int idx = i * 256 + tid;             // 512 int4s = 64 n x 8 segs
        int nn = idx >> 3, seg = idx & 7;
        *(int4*)&g_h_t[(size_t)(n0 + nn) * N_NODES + m0 + seg * 8] =
            *(int4*)&tT[nn * 136 + seg * 8];
    }
}

// ---------------- kernel B: node scores ----------------
__global__ __launch_bounds__(256) void node_stats2(const float* __restrict__ h) {
    __shared__ float sh_h[16][257];
    __shared__ float sh_wa[256][17];
    int tid = threadIdx.x;
    int n0 = blockIdx.x * 16;
#pragma unroll
    for (int q = 0; q < 16; q++) {
        int idx = q * 256 + tid;
        sh_h[idx >> 8][idx & 255] = h[(size_t)n0 * 256 + idx];
        sh_wa[idx >> 4][idx & 15] = Wa_g[idx];
    }
    __syncthreads();
    int nl = tid >> 4, c = tid & 15;
    float s = 0.f;
#pragma unroll 8
    for (int k = 0; k < 256; k++) s += sh_h[nl][k] * sh_wa[k][c];
    int n = n0 + nl;
    if (c < 8) {
        PR_g[c * N_NODES + n] = __floats2half2_rn(expf(s), expf(0.2f * s));
    } else {
        qg[(c - 8) * N_NODES + n] = __float2half(expf(s));
        tg[(c - 8) * N_NODES + n] = __float2half(expf(0.2f * s));
    }
}

// ---------------- attn helpers ----------------
__device__ __forceinline__ void mma16816(float* c, unsigned a0, unsigned a1,
                                         unsigned a2, unsigned a3,
                                         unsigned b0, unsigned b1) {
    asm volatile(
        "mma.sync.aligned.m16n8k16.row.col.f32.f16.f16.f32 "
        "{%0,%1,%2,%3}, {%4,%5,%6,%7}, {%8,%9}, {%0,%1,%2,%3};"
        : "+f"(c[0]), "+f"(c[1]), "+f"(c[2]), "+f"(c[3])
        : "r"(a0), "r"(a1), "r"(a2), "r"(a3), "r"(b0), "r"(b1));
}

__device__ __forceinline__ void ldsm_x4(unsigned* r, unsigned addr) {
    asm volatile(
        "ldmatrix.sync.aligned.m8n8.x4.shared.b16 {%0,%1,%2,%3}, [%4];"
        : "=r"(r[0]), "=r"(r[1]), "=r"(r[2]), "=r"(r[3]) : "r"(addr));
}

__device__ __forceinline__ unsigned expand2(unsigned b) {
    return (b & 1u) * 0xFFFFu + (b & 2u) * 0x7FFF8000u;
}

__device__ __forceinline__ unsigned wpair(__half2 P2, __half2 R2,
                                          unsigned q2, unsigned t2) {
    __half2 qq = *(__half2*)&q2, tt = *(__half2*)&t2;
    __half2 u = __hmax2(__hmul2(P2, qq), __hmul2(R2, tt));
    return *(unsigned*)&u;
}

__device__ __forceinline__ void cp_async4(unsigned dst, const void* src) {
    asm volatile("cp.async.ca.shared.global [%0], [%1], 4;" :: "r"(dst), "l"(src));
}
__device__ __forceinline__ void cp_async8(unsigned dst, const void* src) {
    asm volatile("cp.async.ca.shared.global [%0], [%1], 8;" :: "r"(dst), "l"(src));
}
__device__ __forceinline__ void cp_commit() {
    asm volatile("cp.async.commit_group;" ::: "memory");
}
__device__ __forceinline__ void cp_wait0() {
    asm volatile("cp.async.wait_group 0;" ::: "memory");
}

// buffer (4 heads): gTs 34816 | jq 1024 | jt 1024 | adjb 1024 | masks 16384 = 54272 ; x2
#define OFF_GT     0
#define OFF_JQ     34816
#define OFF_JT     35840
#define OFF_ADJB   36864
#define OFF_MASK   37888
#define BUF_SZ     54272
#define SMEM2_SZ   (2 * BUF_SZ)

extern __shared__ char smem2[];

// grid (4, 64): bx&1 = head-group, bx>>1 = chunk. 512 threads, 2 CTAs/SM.  (R12 proven config)
__global__ __launch_bounds__(512, 2) void attn_agg() {
    int tid  = threadIdx.x;
    int warp = tid >> 5, lane = tid & 31;
    int gid  = lane >> 2, tig = lane & 3;
    int lh   = warp & 3;           // local head (0..3)
    int mtg  = warp >> 2;          // m16 tile (0..3)
    int hg   = blockIdx.x & 1;     // head group
    int chunk = blockIdx.x >> 1;
    int ghead = hg * 4 + lh;
    int i0   = blockIdx.y * ITILE;
    int jstart = chunk * JCHUNK;

    unsigned sbase = (unsigned)__cvta_generic_to_shared(smem2);

    auto stage = [&](int t) {
        int j0 = jstart + t * JT;
        unsigned b = sbase + (t & 1) * BUF_SZ;
#pragma unroll
        for (int q = 0; q < 8; q++) {             // gTs: 4096 x 8B (4 heads x 32 f)
            int idx = q * 512 + tid;
            int hf = idx >> 5, j4 = idx & 31;
            cp_async8(b + OFF_GT + (hf * 136 + j4 * 4) * 2,
                      &g_h_t[(size_t)(hg * 128 + hf) * N_NODES + j0 + j4 * 4]);
        }
        if (tid < 256) {                          // jq, jt tables
            int h2 = tid >> 6, o = tid & 63;
            cp_async4(b + OFF_JQ + tid * 4, &qg[(hg * 4 + h2) * N_NODES + j0 + o * 2]);
            cp_async4(b + OFF_JT + tid * 4, &tg[(hg * 4 + h2) * N_NODES + j0 + o * 2]);
        }
        if (tid < 256) {                          // adjb raw: 64 rows x 4 words
            int r = tid >> 2, cw = tid & 3;
            cp_async4(b + OFF_ADJB + tid * 4,
                      &adj_bits[(i0 + r) * 128 + (j0 >> 5) + cw]);
        }
        cp_commit();
    };

    // per-row broadcast params
    __half2 P2[2], R2[2];
#pragma unroll
    for (int rh = 0; rh < 2; rh++) {
        int r = i0 + mtg * 16 + rh * 8 + gid;
        __half2 pr = PR_g[ghead * N_NODES + r];
        P2[rh] = __half2half2(__low2half(pr));
        R2[rh] = __half2half2(__high2half(pr));
    }

    int ntl = lane >> 4, hb = (lane >> 3) & 1, rowl = lane & 7;
    unsigned lds_off0 = ((lh * 32 + ntl * 8 + rowl) * 136 + hb * 8) * 2;
    unsigned lds_off1 = lds_off0 + 16 * 136 * 2;

    float c[4][4] = {};
    float cz[4] = {};
    const unsigned ONES = 0x3C003C00u;

    stage(0);

    for (int t = 0; t < NTILES; t++) {
        cp_wait0();
        __syncthreads();
        if (t + 1 < NTILES) stage(t + 1);

        char* buf = smem2 + (t & 1) * BUF_SZ;
        {   // expand adjacency bits -> masks (2 slots/thread, 1024 total)
            const unsigned* adjb = (const unsigned*)(buf + OFF_ADJB);
#pragma unroll
            for (int q = 0; q < 2; q++) {
                int slot = q * 512 + tid;
                int emtg = slot >> 8, eks = (slot >> 5) & 7;
                int egid = (slot >> 2) & 7, etig = slot & 3;
                int ewc = eks >> 1, esh = (eks & 1) * 16 + etig * 2;
                unsigned bw0 = adjb[(emtg * 16 + egid) * 4 + ewc] >> esh;
                unsigned bw1 = adjb[(emtg * 16 + egid + 8) * 4 + ewc] >> esh;
                uint4 m;
                m.x = expand2(bw0 & 3u);
                m.y = expand2(bw1 & 3u);
                m.z = expand2((bw0 >> 8) & 3u);
                m.w = expand2((bw1 >> 8) & 3u);
                ((uint4*)(buf + OFF_MASK))[slot] = m;
            }
        }
        __syncthreads();

        const __half* jqp = (const __half*)(buf + OFF_JQ);
        const __half* jtp = (const __half*)(buf + OFF_JT);
        const uint4*  mk  = (const uint4*)(buf + OFF_MASK);
        unsigned gtb = sbase + (t & 1) * BUF_SZ + OFF_GT;

#pragma unroll
        for (int ks = 0; ks < 8; ks++) {
            unsigned bf[8];
            ldsm_x4(bf,     gtb + lds_off0 + ks * 32);   // nt 0,1
            ldsm_x4(bf + 4, gtb + lds_off1 + ks * 32);   // nt 2,3

            int jo = lh * 128 + ks * 16 + tig * 2;
            unsigned qlo = *(const unsigned*)(jqp + jo);
            unsigned qhi = *(const unsigned*)(jqp + jo + 8);
            unsigned tlo = *(const unsigned*)(jtp + jo);
            unsigned thi = *(const unsigned*)(jtp + jo + 8);

            uint4 mm = mk[mtg * 256 + ks * 32 + gid * 4 + tig];

            unsigned a0 = wpair(P2[0], R2[0], qlo, tlo) & mm.x;
            unsigned a1 = wpair(P2[1], R2[1], qlo, tlo) & mm.y;
            unsigned a2 = wpair(P2[0], R2[0], qhi, thi) & mm.z;
            unsigned a3 = wpair(P2[1], R2[1], qhi, thi) & mm.w;

#pragma unroll
            for (int nt = 0; nt < 4; nt++)
                mma16816(c[nt], a0, a1, a2, a3, bf[nt * 2], bf[nt * 2 + 1]);
            mma16816(cz, a0, a1, a2, a3, ONES, ONES);
        }
    }

    // ---- epilogue ----
#pragma unroll
    for (int nt = 0; nt < 4; nt++) {
        int r0 = i0 + mtg * 16 + gid;
        int col = ghead * 32 + nt * 8 + tig * 2;
        *(float2*)(&num_part[chunk][r0][col])     = make_float2(c[nt][0], c[nt][1]);
        *(float2*)(&num_part[chunk][r0 + 8][col]) = make_float2(c[nt][2], c[nt][3]);
    }
    if (tig == 0) {
        int r0 = i0 + mtg * 16 + gid;
        z_part[chunk][ghead][r0]     = cz[0];
        z_part[chunk][ghead][r0 + 8] = cz[2];
    }
}

// ---------------- finalize ----------------
__global__ __launch_bounds__(256) void finalize(float* __restrict__ out) {
    int idx = blockIdx.x * 256 + threadIdx.x;
    int i = idx >> 6, c4 = idx & 63;
    int head = c4 >> 3;
    float4 n0 = *(const float4*)&num_part[0][i][c4 * 4];
    float4 n1 = *(const float4*)&num_part[1][i][c4 * 4];
    float zz = z_part[0][head][i] + z_part[1][head][i];
    float inv = 1.f / zz;
    float4 o;
    o.x = (n0.x + n1.x) * inv;
    o.y = (n0.y + n1.y) * inv;
    o.z = (n0.z + n1.z) * inv;
    o.w = (n0.w + n1.w) * inv;
    *(float4*)&out[(size_t)i * OUTF + c4 * 4] = o;
}

// ---------------- launcher ----------------
extern "C" void kernel_launch(void* const* d_in, const int* in_sizes, int n_in,
                              void* d_out, int out_size) {
    const float* h   = (const float*)d_in[0];
    const int*   adj = (const int*)d_in[1];
    const float* W   = (const float*)d_in[2];
    const float* a   = (const float*)d_in[3];
    float* out = (float*)d_out;

    cudaFuncSetAttribute(attn_agg, cudaFuncAttributeMaxDynamicSharedMemorySize, SMEM2_SZ);
    cudaFuncSetAttribute(prep_fused, cudaFuncAttributeMaxDynamicSharedMemorySize, PREP_SMEM);

    prep_fused<<<2336, 256, PREP_SMEM>>>(h, W, a, adj);   // wa | gemm | adj, concurrent
    node_stats2<<<256, 256>>>(h);
    attn_agg<<<dim3(4, 64), 512, SMEM2_SZ>>>();
    finalize<<<1024, 256>>>(out);
}

// round 16
// speedup vs baseline: 1.0609x; 1.0609x over previous
#include <cuda_runtime.h>
#include <cuda_fp16.h>

#define N_NODES 4096
#define HEADS   8
#define OUTF    256
#define NCHUNK  2
#define JT      128
#define ITILE   64
#define JCHUNK  (N_NODES / NCHUNK)
#define NTILES  (JCHUNK / JT)

// ---------------- device scratch ----------------
__device__ __align__(16) __half   g_h_t[OUTF * N_NODES];       // [h*32+f][n] fp16
__device__ __align__(16) float    Wa_g[256 * 16];
__device__ __align__(16) __half2  PR_g[HEADS * N_NODES];
__device__ __align__(16) __half   qg[HEADS * N_NODES];
__device__ __align__(16) __half   tg[HEADS * N_NODES];
__device__ __align__(16) unsigned adj_bits[N_NODES * (N_NODES / 32)];
__device__ __align__(16) float    num_part[NCHUNK][N_NODES][OUTF];
__device__ __align__(16) float    z_part[NCHUNK][HEADS][N_NODES];

// ---------------- kernel 0: adjacency -> bitmask ----------------
__global__ __launch_bounds__(256) void adj_to_bits(const int* __restrict__ adj) {
    int warp = threadIdx.x >> 5, lane = threadIdx.x & 31;
    int gw = blockIdx.x * 8 + warp;
    int i = gw >> 2, wbase = (gw & 3) * 32;
#pragma unroll 8
    for (int k = 0; k < 32; k++) {
        int v = adj[(size_t)i * N_NODES + (wbase + k) * 32 + lane];
        unsigned b = __ballot_sync(0xffffffffu, v != 0);
        if (lane == 0) adj_bits[i * 128 + wbase + k] = b;
    }
}

// ---------------- kernel A: Wa ----------------
__global__ __launch_bounds__(256) void compute_wa(const float* __restrict__ W,
                                                  const float* __restrict__ a) {
    int warp = threadIdx.x >> 5, lane = threadIdx.x & 31;
    int k = blockIdx.x * 8 + warp;
    float wrow[8];
#pragma unroll
    for (int hd = 0; hd < 8; hd++) wrow[hd] = W[(size_t)k * 256 + hd * 32 + lane];
    float asrc = a[lane], adst = a[32 + lane];
#pragma unroll
    for (int c = 0; c < 16; c++) {
        float v = wrow[c & 7] * ((c < 8) ? asrc : adst);
#pragma unroll
        for (int o = 16; o; o >>= 1) v += __shfl_xor_sync(0xffffffffu, v, o);
        if (lane == 0) Wa_g[k * 16 + c] = v;
    }
}

// ---------------- kernel B: node scores ----------------
__global__ __launch_bounds__(256) void node_stats2(const float* __restrict__ h) {
    __shared__ float sh_h[16][257];
    __shared__ float sh_wa[256][17];
    int tid = threadIdx.x;
    int n0 = blockIdx.x * 16;
#pragma unroll
    for (int q = 0; q < 16; q++) {
        int idx = q * 256 + tid;
        sh_h[idx >> 8][idx & 255] = h[(size_t)n0 * 256 + idx];
        sh_wa[idx >> 4][idx & 15] = Wa_g[idx];
    }
    __syncthreads();
    int nl = tid >> 4, c = tid & 15;
    float s = 0.f;
#pragma unroll 8
    for (int k = 0; k < 256; k++) s += sh_h[nl][k] * sh_wa[k][c];
    int n = n0 + nl;
    if (c < 8) {
        PR_g[c * N_NODES + n] = __floats2half2_rn(expf(s), expf(0.2f * s));
    } else {
        qg[(c - 8) * N_NODES + n] = __float2half(expf(s));
        tg[(c - 8) * N_NODES + n] = __float2half(expf(0.2f * s));
    }
}

// ---------------- kernel 1: g = h @ W via tf32 (128m x 64n) ----------------
__device__ __forceinline__ unsigned tf32r(float x) {
    unsigned y;
    asm("cvt.rna.tf32.f32 %0, %1;" : "=r"(y) : "f"(x));
    return y;
}

__device__ __forceinline__ void mma_tf32(float* c, unsigned a0, unsigned a1,
                                         unsigned a2, unsigned a3,
                                         unsigned b0, unsigned b1) {
    asm volatile(
        "mma.sync.aligned.m16n8k8.row.col.f32.tf32.tf32.f32 "
        "{%0,%1,%2,%3}, {%4,%5,%6,%7}, {%8,%9}, {%0,%1,%2,%3};"
        : "+f"(c[0]), "+f"(c[1]), "+f"(c[2]), "+f"(c[3])
        : "r"(a0), "r"(a1), "r"(a2), "r"(a3), "r"(b0), "r"(b1));
}

#define GEMM_SMEM (69632 + 36864)

__global__ __launch_bounds__(256, 1) void gemm_g_tc(const float* __restrict__ h,
                                                    const float* __restrict__ W) {
    extern __shared__ unsigned smg[];
    unsigned* sh_w = smg;                    // [k(256)][68]
    unsigned* sh_h = smg + 256 * 68;         // [2][m(128)][36]
    __half* tT = (__half*)smg;               // epilogue alias: [64][136] halves

    int tid = threadIdx.x;
    int warp = tid >> 5, lane = tid & 31;
    int gid = lane >> 2, tig = lane & 3;
    int wm = warp >> 1, wn = warp & 1;
    int n0 = blockIdx.x * 64, m0 = blockIdx.y * 128;

#pragma unroll
    for (int i = 0; i < 16; i++) {
        int idx = i * 256 + tid;
        int k = idx >> 4, seg = idx & 15;
        float4 v = *(const float4*)&W[(size_t)k * 256 + n0 + seg * 4];
        uint4 u = make_uint4(tf32r(v.x), tf32r(v.y), tf32r(v.z), tf32r(v.w));
        *(uint4*)&sh_w[k * 68 + seg * 4] = u;
    }

    float4 hreg[4];
    auto ldh = [&](int kc) {
#pragma unroll
        for (int i = 0; i < 4; i++) {
            int idx = i * 256 + tid;
            int m = idx >> 3, seg = idx & 7;
            hreg[i] = *(const float4*)&h[(size_t)(m0 + m) * 256 + kc * 32 + seg * 4];
        }
    };
    auto sth = [&](int b) {
        unsigned* dst = sh_h + b * 128 * 36;
#pragma unroll
        for (int i = 0; i < 4; i++) {
            int idx = i * 256 + tid;
            int m = idx >> 3, seg = idx & 7;
            float4 v = hreg[i];
            uint4 u = make_uint4(tf32r(v.x), tf32r(v.y), tf32r(v.z), tf32r(v.w));
            *(uint4*)&dst[m * 36 + seg * 4] = u;
        }
    };

    float c[2][4][4] = {};

    ldh(0);
    for (int kc = 0; kc < 8; kc++) {
        sth(kc & 1);
        __syncthreads();
        if (kc < 7) ldh(kc + 1);

        const unsigned* A = sh_h + (kc & 1) * 128 * 36;
#pragma unroll
        for (int ks = 0; ks < 4; ks++) {
            unsigned b0[4], b1[4];
            int kb = kc * 32 + ks * 8 + tig;
#pragma unroll
            for (int nt = 0; nt < 4; nt++) {
                int nn = wn * 32 + nt * 8 + gid;
                b0[nt] = sh_w[kb * 68 + nn];
                b1[nt] = sh_w[(kb + 4) * 68 + nn];
            }
#pragma unroll
            for (int mt = 0; mt < 2; mt++) {
                int r0 = (wm * 32 + mt * 16 + gid) * 36 + ks * 8 + tig;
                unsigned a0 = A[r0];
                unsigned a1 = A[r0 + 8 * 36];
                unsigned a2 = A[r0 + 4];
                unsigned a3 = A[r0 + 8 * 36 + 4];
#pragma unroll
                for (int nt = 0; nt < 4; nt++)
                    mma_tf32(c[mt][nt], a0, a1, a2, a3, b0[nt], b1[nt]);
            }
        }
        __syncthreads();
    }

#pragma unroll
    for (int mt = 0; mt < 2; mt++)
#pragma unroll
        for (int nt = 0; nt < 4; nt++) {
            int nn = wn * 32 + nt * 8 + tig * 2;
            int mm = wm * 32 + mt * 16 + gid;
            tT[nn * 136 + mm]           = __float2half(c[mt][nt][0]);
            tT[(nn + 1) * 136 + mm]     = __float2half(c[mt][nt][1]);
            tT[nn * 136 + mm + 8]       = __float2half(c[mt][nt][2]);
            tT[(nn + 1) * 136 + mm + 8] = __float2half(c[mt][nt][3]);
        }
    __syncthreads();
#pragma unroll
    for (int i = 0; i < 4; i++) {
        int idx = i * 256 + tid;
        int nn = idx >> 4, seg = idx & 15;
        *(int4*)&g_h_t[(size_t)(n0 + nn) * N_NODES + m0 + seg * 8] =
            *(int4*)&tT[nn * 136 + seg * 8];
    }
}

// ---------------- kernel 2 helpers ----------------
__device__ __forceinline__ void mma16816(float* c, unsigned a0, unsigned a1,
                                         unsigned a2, unsigned a3,
                                         unsigned b0, unsigned b1) {
    asm volatile(
        "mma.sync.aligned.m16n8k16.row.col.f32.f16.f16.f32 "
        "{%0,%1,%2,%3}, {%4,%5,%6,%7}, {%8,%9}, {%0,%1,%2,%3};"
        : "+f"(c[0]), "+f"(c[1]), "+f"(c[2]), "+f"(c[3])
        : "r"(a0), "r"(a1), "r"(a2), "r"(a3), "r"(b0), "r"(b1));
}

__device__ __forceinline__ void ldsm_x4(unsigned* r, unsigned addr) {
    asm volatile(
        "ldmatrix.sync.aligned.m8n8.x4.shared.b16 {%0,%1,%2,%3}, [%4];"
        : "=r"(r[0]), "=r"(r[1]), "=r"(r[2]), "=r"(r[3]) : "r"(addr));
}

__device__ __forceinline__ unsigned expand2(unsigned b) {
    return (b & 1u) * 0xFFFFu + (b & 2u) * 0x7FFF8000u;
}

__device__ __forceinline__ unsigned wpair(__half2 P2, __half2 R2,
                                          unsigned q2, unsigned t2) {
    __half2 qq = *(__half2*)&q2, tt = *(__half2*)&t2;
    __half2 u = __hmax2(__hmul2(P2, qq), __hmul2(R2, tt));
    return *(unsigned*)&u;
}

__device__ __forceinline__ void cp_async4(unsigned dst, const void* src) {
    asm volatile("cp.async.ca.shared.global [%0], [%1], 4;" :: "r"(dst), "l"(src));
}
__device__ __forceinline__ void cp_async8(unsigned dst, const void* src) {
    asm volatile("cp.async.ca.shared.global [%0], [%1], 8;" :: "r"(dst), "l"(src));
}
__device__ __forceinline__ void cp_commit() {
    asm volatile("cp.async.commit_group;" ::: "memory");
}
__device__ __forceinline__ void cp_wait0() {
    asm volatile("cp.async.wait_group 0;" ::: "memory");
}

// buffer (4 heads): gTs 34816 | jq 1024 | jt 1024 | adjb 1024 | masks 16384 = 54272 ; x2
#define OFF_GT     0
#define OFF_JQ     34816
#define OFF_JT     35840
#define OFF_ADJB   36864
#define OFF_MASK   37888
#define BUF_SZ     54272
#define SMEM2_SZ   (2 * BUF_SZ)

extern __shared__ char smem2[];

// grid (4, 64): bx&1 = head-group, bx>>1 = chunk. 512 threads, 2 CTAs/SM.  (R12 proven config)
__global__ __launch_bounds__(512, 2) void attn_agg() {
    int tid  = threadIdx.x;
    int warp = tid >> 5, lane = tid & 31;
    int gid  = lane >> 2, tig = lane & 3;
    int lh   = warp & 3;           // local head (0..3)
    int mtg  = warp >> 2;          // m16 tile (0..3)
    int hg   = blockIdx.x & 1;     // head group
    int chunk = blockIdx.x >> 1;
    int ghead = hg * 4 + lh;
    int i0   = blockIdx.y * ITILE;
    int jstart = chunk * JCHUNK;

    unsigned sbase = (unsigned)__cvta_generic_to_shared(smem2);

    auto stage = [&](int t) {
        int j0 = jstart + t * JT;
        unsigned b = sbase + (t & 1) * BUF_SZ;
#pragma unroll
        for (int q = 0; q < 8; q++) {             // gTs: 4096 x 8B (4 heads x 32 f)
            int idx = q * 512 + tid;
            int hf = idx >> 5, j4 = idx & 31;
            cp_async8(b + OFF_GT + (hf * 136 + j4 * 4) * 2,
                      &g_h_t[(size_t)(hg * 128 + hf) * N_NODES + j0 + j4 * 4]);
        }
        if (tid < 256) {                          // jq, jt tables
            int h2 = tid >> 6, o = tid & 63;
            cp_async4(b + OFF_JQ + tid * 4, &qg[(hg * 4 + h2) * N_NODES + j0 + o * 2]);
            cp_async4(b + OFF_JT + tid * 4, &tg[(hg * 4 + h2) * N_NODES + j0 + o * 2]);
        }
        if (tid < 256) {                          // adjb raw: 64 rows x 4 words
            int r = tid >> 2, cw = tid & 3;
            cp_async4(b + OFF_ADJB + tid * 4,
                      &adj_bits[(i0 + r) * 128 + (j0 >> 5) + cw]);
        }
        cp_commit();
    };

    // per-row broadcast params
    __half2 P2[2], R2[2];
#pragma unroll
    for (int rh = 0; rh < 2; rh++) {
        int r = i0 + mtg * 16 + rh * 8 + gid;
        __half2 pr = PR_g[ghead * N_NODES + r];
        P2[rh] = __half2half2(__low2half(pr));
        R2[rh] = __half2half2(__high2half(pr));
    }

    int ntl = lane >> 4, hb = (lane >> 3) & 1, rowl = lane & 7;
    unsigned lds_off0 = ((lh * 32 + ntl * 8 + rowl) * 136 + hb * 8) * 2;
    unsigned lds_off1 = lds_off0 + 16 * 136 * 2;

    float c[4][4] = {};
    float cz[4] = {};
    const unsigned ONES = 0x3C003C00u;

    stage(0);

    for (int t = 0; t < NTILES; t++) {
        cp_wait0();
        __syncthreads();
        if (t + 1 < NTILES) stage(t + 1);

        char* buf = smem2 + (t & 1) * BUF_SZ;
        {   // expand adjacency bits -> masks (2 slots/thread, 1024 total)
            const unsigned* adjb = (const unsigned*)(buf + OFF_ADJB);
#pragma unroll
            for (int q = 0; q < 2; q++) {
                int slot = q * 512 + tid;
                int emtg = slot >> 8, eks = (slot >> 5) & 7;
                int egid = (slot >> 2) & 7, etig = slot & 3;
                int ewc = eks >> 1, esh = (eks & 1) * 16 + etig * 2;
                unsigned bw0 = adjb[(emtg * 16 + egid) * 4 + ewc] >> esh;
                unsigned bw1 = adjb[(emtg * 16 + egid + 8) * 4 + ewc] >> esh;
                uint4 m;
                m.x = expand2(bw0 & 3u);
                m.y = expand2(bw1 & 3u);
                m.z = expand2((bw0 >> 8) & 3u);
                m.w = expand2((bw1 >> 8) & 3u);
                ((uint4*)(buf + OFF_MASK))[slot] = m;
            }
        }
        __syncthreads();

        const __half* jqp = (const __half*)(buf + OFF_JQ);
        const __half* jtp = (const __half*)(buf + OFF_JT);
        const uint4*  mk  = (const uint4*)(buf + OFF_MASK);
        unsigned gtb = sbase + (t & 1) * BUF_SZ + OFF_GT;

#pragma unroll
        for (int ks = 0; ks < 8; ks++) {
            unsigned bf[8];
            ldsm_x4(bf,     gtb + lds_off0 + ks * 32);   // nt 0,1
            ldsm_x4(bf + 4, gtb + lds_off1 + ks * 32);   // nt 2,3

            int jo = lh * 128 + ks * 16 + tig * 2;
            unsigned qlo = *(const unsigned*)(jqp + jo);
            unsigned qhi = *(const unsigned*)(jqp + jo + 8);
            unsigned tlo = *(const unsigned*)(jtp + jo);
            unsigned thi = *(const unsigned*)(jtp + jo + 8);

            uint4 mm = mk[mtg * 256 + ks * 32 + gid * 4 + tig];

            unsigned a0 = wpair(P2[0], R2[0], qlo, tlo) & mm.x;
            unsigned a1 = wpair(P2[1], R2[1], qlo, tlo) & mm.y;
            unsigned a2 = wpair(P2[0], R2[0], qhi, thi) & mm.z;
            unsigned a3 = wpair(P2[1], R2[1], qhi, thi) & mm.w;

#pragma unroll
            for (int nt = 0; nt < 4; nt++)
                mma16816(c[nt], a0, a1, a2, a3, bf[nt * 2], bf[nt * 2 + 1]);
            mma16816(cz, a0, a1, a2, a3, ONES, ONES);
        }
    }

    // ---- epilogue ----
#pragma unroll
    for (int nt = 0; nt < 4; nt++) {
        int r0 = i0 + mtg * 16 + gid;
        int col = ghead * 32 + nt * 8 + tig * 2;
        *(float2*)(&num_part[chunk][r0][col])     = make_float2(c[nt][0], c[nt][1]);
        *(float2*)(&num_part[chunk][r0 + 8][col]) = make_float2(c[nt][2], c[nt][3]);
    }
    if (tig == 0) {
        int r0 = i0 + mtg * 16 + gid;
        z_part[chunk][ghead][r0]     = cz[0];
        z_part[chunk][ghead][r0 + 8] = cz[2];
    }
}

// ---------------- kernel 3: combine + divide (MLP-batched) ----------------
__global__ __launch_bounds__(256) void finalize(float* __restrict__ out) {
    int base = blockIdx.x * 256 + threadIdx.x;    // 65536 threads x 4 groups
    float4 n0[4], n1[4];
    float  zz[4];
#pragma unroll
    for (int q = 0; q < 4; q++) {
        int idx = base + q * 65536;
        int i = idx >> 6, c4 = idx & 63;
        n0[q] = *(const float4*)&num_part[0][i][c4 * 4];
        n1[q] = *(const float4*)&num_part[1][i][c4 * 4];
        zz[q] = z_part[0][c4 >> 3][i] + z_part[1][c4 >> 3][i];
    }
#pragma unroll
    for (int q = 0; q < 4; q++) {
        int idx = base + q * 65536;
        int i = idx >> 6, c4 = idx & 63;
        float inv = 1.f / zz[q];
        float4 o;
        o.x = (n0[q].x + n1[q].x) * inv;
        o.y = (n0[q].y + n1[q].y) * inv;
        o.z = (n0[q].z + n1[q].z) * inv;
        o.w = (n0[q].w + n1[q].w) * inv;
        *(float4*)&out[(size_t)i * OUTF + c4 * 4] = o;
    }
}

// ---------------- launcher ----------------
extern "C" void kernel_launch(void* const* d_in, const int* in_sizes, int n_in,
                              void* d_out, int out_size) {
    const float* h   = (const float*)d_in[0];
    const int*   adj = (const int*)d_in[1];
    const float* W   = (const float*)d_in[2];
    const float* a   = (const float*)d_in[3];
    float* out = (float*)d_out;

    cudaFuncSetAttribute(attn_agg, cudaFuncAttributeMaxDynamicSharedMemorySize, SMEM2_SZ);
    cudaFuncSetAttribute(gemm_g_tc, cudaFuncAttributeMaxDynamicSharedMemorySize, GEMM_SMEM);

    adj_to_bits<<<2048, 256>>>(adj);
    compute_wa<<<32, 256>>>(W, a);
    node_stats2<<<256, 256>>>(h);
    gemm_g_tc<<<dim3(4, 32), 256, GEMM_SMEM>>>(h, W);
    attn_agg<<<dim3(4, 64), 512, SMEM2_SZ>>>();
    finalize<<<256, 256>>>(out);
}